// round 17
// baseline (speedup 1.0000x reference)
#include <cuda_runtime.h>
#include <cstdint>

#define Bb 16
#define Nn 16
#define Hh 512
#define Ww 512
#define HW (Hh * Ww)
#define HW4 (HW / 4)        // 65536 float4 per (b,n) slice
#define W4 (Ww / 4)         // 128 float4 per row
#define THREADS 256
#define NG 2
#define NGROUPS (Nn / NG)   // 8
#define SPLIT 8
#define CHUNK (HW4 / SPLIT) // 8192 float4 per block per stream
#define UB 4                // load batch
#define OUTER (CHUNK / (THREADS * UB))  // 8
#define GRID (Bb * NGROUPS * SPLIT)     // 1024

__device__ float    g_ov[Bb * Nn];
__device__ float    g_it[Bb * Nn];
__device__ float    g_ts[Bb * Nn];   // counted once per (b,split) by ng==0 blocks
__device__ unsigned g_done;

__global__ __launch_bounds__(THREADS)
void stream_kernel(const float* __restrict__ masks,
                   const float* __restrict__ target,
                   const int*   __restrict__ boxes,
                   float*       __restrict__ out)
{
    const int blk   = blockIdx.x;        // 0..1023
    const int b     = blk >> 6;          // / (NGROUPS*SPLIT)
    const int rest  = blk & 63;
    const int ng    = rest >> 3;         // 0..7
    const int split = rest & 7;          // 0..7

    const int tid = threadIdx.x;
    const int base = split * CHUNK;
    const int n0 = ng * NG;

    const float4* __restrict__ mp0 = (const float4*)masks + ((size_t)(b * Nn + n0 + 0)) * HW4 + base + tid;
    const float4* __restrict__ mp1 = (const float4*)masks + ((size_t)(b * Nn + n0 + 1)) * HW4 + base + tid;
    const float4* __restrict__ tp  = (const float4*)target + (size_t)b * HW4 + base + tid;

    const int4 bxA = __ldg((const int4*)boxes + b * Nn + n0 + 0);
    const int4 bxB = __ldg((const int4*)boxes + b * Nn + n0 + 1);

    // k-invariant column selectors for this thread's float4 lane (both boxes)
    const int w0 = (tid & (W4 - 1)) << 2;
    const float a0 = (w0     >= bxA.x && w0     < bxA.z) ? 1.f : 0.f;
    const float a1 = (w0 + 1 >= bxA.x && w0 + 1 < bxA.z) ? 1.f : 0.f;
    const float a2 = (w0 + 2 >= bxA.x && w0 + 2 < bxA.z) ? 1.f : 0.f;
    const float a3 = (w0 + 3 >= bxA.x && w0 + 3 < bxA.z) ? 1.f : 0.f;
    const float b0 = (w0     >= bxB.x && w0     < bxB.z) ? 1.f : 0.f;
    const float b1 = (w0 + 1 >= bxB.x && w0 + 1 < bxB.z) ? 1.f : 0.f;
    const float b2 = (w0 + 2 >= bxB.x && w0 + 2 < bxB.z) ? 1.f : 0.f;
    const float b3 = (w0 + 3 >= bxB.x && w0 + 3 < bxB.z) ? 1.f : 0.f;

    // row index: advances by 2 per k-step (stride 256 float4 = 2 rows)
    int h = (base >> 7) + (tid >> 7);

    float ov0 = 0.f, ov1 = 0.f, it0 = 0.f, it1 = 0.f, ts = 0.f;

    for (int kk = 0; kk < OUTER; kk++) {
        float4 mv0[UB], mv1[UB], tv[UB];
        #pragma unroll
        for (int u = 0; u < UB; u++) {
            mv0[u] = __ldcs(mp0 + u * THREADS);   // streaming, evict-first
            mv1[u] = __ldcs(mp1 + u * THREADS);
            tv[u]  = __ldg(tp + u * THREADS);     // L2-resident
        }
        mp0 += UB * THREADS;
        mp1 += UB * THREADS;
        tp  += UB * THREADS;

        #pragma unroll
        for (int u = 0; u < UB; u++) {
            ov0 = fmaf(mv0[u].x, tv[u].x, ov0); ov0 = fmaf(mv0[u].y, tv[u].y, ov0);
            ov0 = fmaf(mv0[u].z, tv[u].z, ov0); ov0 = fmaf(mv0[u].w, tv[u].w, ov0);
            ov1 = fmaf(mv1[u].x, tv[u].x, ov1); ov1 = fmaf(mv1[u].y, tv[u].y, ov1);
            ov1 = fmaf(mv1[u].z, tv[u].z, ov1); ov1 = fmaf(mv1[u].w, tv[u].w, ov1);

            ts += (tv[u].x + tv[u].y) + (tv[u].z + tv[u].w);

            const int hu = h + 2 * u;
            if (hu >= bxA.y && hu < bxA.w) {     // warp-uniform
                float s;
                s = fmaf(a0, tv[u].x, 0.f);
                s = fmaf(a1, tv[u].y, s);
                s = fmaf(a2, tv[u].z, s);
                s = fmaf(a3, tv[u].w, s);
                it0 += s;
            }
            if (hu >= bxB.y && hu < bxB.w) {
                float s;
                s = fmaf(b0, tv[u].x, 0.f);
                s = fmaf(b1, tv[u].y, s);
                s = fmaf(b2, tv[u].z, s);
                s = fmaf(b3, tv[u].w, s);
                it1 += s;
            }
        }
        h += 2 * UB;
    }

    // ---- single block reduction of 5 values ----
    const unsigned FULL = 0xFFFFFFFFu;
    float v[5] = {ov0, ov1, it0, it1, ts};
    #pragma unroll
    for (int q = 0; q < 5; q++) {
        #pragma unroll
        for (int off = 16; off > 0; off >>= 1)
            v[q] += __shfl_xor_sync(FULL, v[q], off);
    }

    __shared__ float s_red[THREADS / 32][5];
    const int wid = tid >> 5;
    const int lid = tid & 31;
    if (lid == 0) {
        #pragma unroll
        for (int q = 0; q < 5; q++) s_red[wid][q] = v[q];
    }
    __syncthreads();

    if (tid < 5) {
        float sum = 0.f;
        #pragma unroll
        for (int w = 0; w < THREADS / 32; w++) sum += s_red[w][tid];
        if (tid == 0)      atomicAdd(&g_ov[b * Nn + n0 + 0], sum);
        else if (tid == 1) atomicAdd(&g_ov[b * Nn + n0 + 1], sum);
        else if (tid == 2) atomicAdd(&g_it[b * Nn + n0 + 0], sum);
        else if (tid == 3) atomicAdd(&g_it[b * Nn + n0 + 1], sum);
        else if (ng == 0)  atomicAdd(&g_ts[b], sum);   // once per (b,split)
    }
    __threadfence();
    __syncthreads();

    __shared__ unsigned s_last;
    if (tid == 0) s_last = atomicAdd(&g_done, 1u);
    __syncthreads();

    // ---- last block finalizes + resets (graph-replay safe) ----
    if (s_last == GRID - 1) {
        const int j = tid;                     // 0..255 = one per bn
        const float ovv = *(volatile float*)&g_ov[j];
        const float itv = *(volatile float*)&g_it[j];
        const float tsv = *(volatile float*)&g_ts[j >> 4];
        const int4 bx = reinterpret_cast<const int4*>(boxes)[j];
        const float area = (float)(bx.z - bx.x) * (float)(bx.w - bx.y);
        const float uni = area + tsv - itv;
        out[j * 2 + 0] = ovv;
        out[j * 2 + 1] = itv / (uni + 1e-8f);
        g_ov[j] = 0.f;
        g_it[j] = 0.f;
        if (j < Bb) g_ts[j] = 0.f;
        if (j == 0) g_done = 0u;
    }
}

extern "C" void kernel_launch(void* const* d_in, const int* in_sizes, int n_in,
                              void* d_out, int out_size)
{
    const float* masks  = (const float*)d_in[0];   // (B,N,H,W) f32
    const float* target = (const float*)d_in[1];   // (B,H,W)   f32
    const int*   boxes  = (const int*)d_in[2];     // (B,N,4)   i32
    float* out = (float*)d_out;                    // (B,N,2)   f32

    stream_kernel<<<GRID, THREADS>>>(masks, target, boxes, out);
}